// round 2
// baseline (speedup 1.0000x reference)
#include <cuda_runtime.h>
#include <math.h>

#define NQc   40000
#define EDc   128
#define NVc   43520

typedef unsigned long long u64;

// ---------------- packed f32x2 helpers ----------------
__device__ __forceinline__ u64 dup2(float x){ u64 r; asm("mov.b64 %0,{%1,%1};":"=l"(r):"f"(x)); return r; }
__device__ __forceinline__ u64 ffma2(u64 a, u64 b, u64 c){ u64 d; asm("fma.rn.f32x2 %0,%1,%2,%3;":"=l"(d):"l"(a),"l"(b),"l"(c)); return d; }
__device__ __forceinline__ float2 unpk(u64 v){ float x,y; asm("mov.b64 {%0,%1},%2;":"=f"(x),"=f"(y):"l"(v)); return make_float2(x,y); }

// ---------------- scratch (no cudaMalloc allowed) ----------------
__device__ float g_q   [NQc*EDc];
__device__ float g_qin [NQc*EDc];
__device__ float g_v   [NVc*EDc];
__device__ float g_off [NQc*512];
__device__ float g_aw  [NQc*256];
__device__ float g_samp[NQc*EDc];
__device__ float g_t1  [NQc*EDc];
__device__ float g_t2  [NQc*EDc];
__device__ float g_c1  [NQc*128];
__device__ float g_c2  [NQc*64];
__device__ float g_c3  [NQc*48];
__device__ float g_c4  [NQc*48];
__device__ float g_wt  [49*128*128];
__device__ float g_part[320*128];
__device__ float g_scale[128];
__device__ float g_shift[128];
__device__ int   g_maxidx;

// ---------------- elementwise ----------------
__global__ void copy_k(float* __restrict__ dst, const float* __restrict__ src, int n){
    int i = blockIdx.x*256 + threadIdx.x; if (i<n) dst[i]=src[i];
}
__global__ void add_k(float* __restrict__ dst, const float* __restrict__ a, const float* __restrict__ b, int n){
    int i = blockIdx.x*256 + threadIdx.x; if (i<n) dst[i]=a[i]+b[i];
}

// ---------------- mask (max over proj_indices) ----------------
__global__ void set_min_k(){ g_maxidx = (-2147483647 - 1); }
__global__ void rmax_k(const int* __restrict__ p, int n){
    int i = blockIdx.x*256 + threadIdx.x;
    int v = (i<n)? p[i] : (-2147483647 - 1);
    #pragma unroll
    for (int o=16;o>0;o>>=1) v = max(v, __shfl_xor_sync(0xffffffffu, v, o));
    __shared__ int sm[8];
    if ((threadIdx.x&31)==0) sm[threadIdx.x>>5]=v;
    __syncthreads();
    if (threadIdx.x==0){
        int m = sm[0];
        #pragma unroll
        for (int j=1;j<8;j++) m = max(m, sm[j]);
        atomicMax(&g_maxidx, m);
    }
}
__global__ void wmask_k(const int* __restrict__ p, float* __restrict__ o, int n){
    int i = blockIdx.x*256 + threadIdx.x;
    if (i<n) o[i] = (p[i] < g_maxidx) ? 1.0f : 0.0f;
}

// =====================================================================
// GEMM: C[M,N] = A[M,K] @ B[K,N] (+bias, opt relu)
// BM=128, BK=16, BN template (128 or 64). NT = 2*BN threads. 8x8 microtile.
// Double-buffered smem, reg-prefetch of next slab.
// =====================================================================
template<int BN, int NT>
__global__ void __launch_bounds__(NT) gemm2_k(
    const float* __restrict__ A, const float* __restrict__ B,
    const float* __restrict__ bias, float* __restrict__ C,
    int M, int N, int K, int relu)
{
    constexpr int TX  = BN/8;           // threads along N
    constexpr int AF4 = 512/NT;         // float4/thread for A slab (128x16)
    constexpr int BF4 = (16*BN/4)/NT;   // float4/thread for B slab (16xBN)
    __shared__ float As[2][16][132];
    __shared__ float Bs[2][16][BN+4];

    int tid = threadIdx.x;
    int bm = blockIdx.y*128, bn = blockIdx.x*BN;
    int tx = tid % TX, ty = tid / TX;

    u64 acc[8][4];
    #pragma unroll
    for (int i=0;i<8;i++)
        #pragma unroll
        for (int j=0;j<4;j++) acc[i][j]=0ull;

    int S = K >> 4;
    float4 ar[AF4], br[BF4];

    // ---- prologue: load slab 0 ----
    #pragma unroll
    for (int j=0;j<AF4;j++){
        int idx = j*NT + tid; int row = idx>>2, kc = idx&3;
        int am = bm + row;
        ar[j] = (am < M) ? *(const float4*)&A[(size_t)am*K + kc*4]
                         : make_float4(0.f,0.f,0.f,0.f);
    }
    #pragma unroll
    for (int j=0;j<BF4;j++){
        int idx = j*NT + tid; int kr = idx/(BN/4), cc = idx%(BN/4);
        br[j] = *(const float4*)&B[(size_t)kr*N + bn + cc*4];
    }
    #pragma unroll
    for (int j=0;j<AF4;j++){
        int idx = j*NT + tid; int row = idx>>2, kc = idx&3;
        As[0][kc*4+0][row]=ar[j].x; As[0][kc*4+1][row]=ar[j].y;
        As[0][kc*4+2][row]=ar[j].z; As[0][kc*4+3][row]=ar[j].w;
    }
    #pragma unroll
    for (int j=0;j<BF4;j++){
        int idx = j*NT + tid; int kr = idx/(BN/4), cc = idx%(BN/4);
        *(float4*)&Bs[0][kr][cc*4] = br[j];
    }
    __syncthreads();

    for (int s=0; s<S; s++){
        int buf = s&1;
        if (s+1 < S){
            int k0 = (s+1)*16;
            #pragma unroll
            for (int j=0;j<AF4;j++){
                int idx = j*NT + tid; int row = idx>>2, kc = idx&3;
                int am = bm + row;
                ar[j] = (am < M) ? *(const float4*)&A[(size_t)am*K + k0 + kc*4]
                                 : make_float4(0.f,0.f,0.f,0.f);
            }
            #pragma unroll
            for (int j=0;j<BF4;j++){
                int idx = j*NT + tid; int kr = idx/(BN/4), cc = idx%(BN/4);
                br[j] = *(const float4*)&B[(size_t)(k0+kr)*N + bn + cc*4];
            }
        }
        #pragma unroll
        for (int kk=0;kk<16;kk++){
            float4 a0 = *(const float4*)&As[buf][kk][ty*8];
            float4 a1 = *(const float4*)&As[buf][kk][ty*8+4];
            ulonglong2 b01 = *(const ulonglong2*)&Bs[buf][kk][tx*8];
            ulonglong2 b23 = *(const ulonglong2*)&Bs[buf][kk][tx*8+4];
            u64 d;
            d=dup2(a0.x); acc[0][0]=ffma2(d,b01.x,acc[0][0]); acc[0][1]=ffma2(d,b01.y,acc[0][1]); acc[0][2]=ffma2(d,b23.x,acc[0][2]); acc[0][3]=ffma2(d,b23.y,acc[0][3]);
            d=dup2(a0.y); acc[1][0]=ffma2(d,b01.x,acc[1][0]); acc[1][1]=ffma2(d,b01.y,acc[1][1]); acc[1][2]=ffma2(d,b23.x,acc[1][2]); acc[1][3]=ffma2(d,b23.y,acc[1][3]);
            d=dup2(a0.z); acc[2][0]=ffma2(d,b01.x,acc[2][0]); acc[2][1]=ffma2(d,b01.y,acc[2][1]); acc[2][2]=ffma2(d,b23.x,acc[2][2]); acc[2][3]=ffma2(d,b23.y,acc[2][3]);
            d=dup2(a0.w); acc[3][0]=ffma2(d,b01.x,acc[3][0]); acc[3][1]=ffma2(d,b01.y,acc[3][1]); acc[3][2]=ffma2(d,b23.x,acc[3][2]); acc[3][3]=ffma2(d,b23.y,acc[3][3]);
            d=dup2(a1.x); acc[4][0]=ffma2(d,b01.x,acc[4][0]); acc[4][1]=ffma2(d,b01.y,acc[4][1]); acc[4][2]=ffma2(d,b23.x,acc[4][2]); acc[4][3]=ffma2(d,b23.y,acc[4][3]);
            d=dup2(a1.y); acc[5][0]=ffma2(d,b01.x,acc[5][0]); acc[5][1]=ffma2(d,b01.y,acc[5][1]); acc[5][2]=ffma2(d,b23.x,acc[5][2]); acc[5][3]=ffma2(d,b23.y,acc[5][3]);
            d=dup2(a1.z); acc[6][0]=ffma2(d,b01.x,acc[6][0]); acc[6][1]=ffma2(d,b01.y,acc[6][1]); acc[6][2]=ffma2(d,b23.x,acc[6][2]); acc[6][3]=ffma2(d,b23.y,acc[6][3]);
            d=dup2(a1.w); acc[7][0]=ffma2(d,b01.x,acc[7][0]); acc[7][1]=ffma2(d,b01.y,acc[7][1]); acc[7][2]=ffma2(d,b23.x,acc[7][2]); acc[7][3]=ffma2(d,b23.y,acc[7][3]);
        }
        if (s+1 < S){
            int nb = buf^1;
            #pragma unroll
            for (int j=0;j<AF4;j++){
                int idx = j*NT + tid; int row = idx>>2, kc = idx&3;
                As[nb][kc*4+0][row]=ar[j].x; As[nb][kc*4+1][row]=ar[j].y;
                As[nb][kc*4+2][row]=ar[j].z; As[nb][kc*4+3][row]=ar[j].w;
            }
            #pragma unroll
            for (int j=0;j<BF4;j++){
                int idx = j*NT + tid; int kr = idx/(BN/4), cc = idx%(BN/4);
                *(float4*)&Bs[nb][kr][cc*4] = br[j];
            }
        }
        __syncthreads();
    }

    // ---- epilogue ----
    int n0 = bn + tx*8;
    float bsv[8];
    #pragma unroll
    for (int j=0;j<8;j++) bsv[j] = bias[n0+j];
    #pragma unroll
    for (int i=0;i<8;i++){
        int m = bm + ty*8 + i;
        if (m >= M) continue;
        float2 p0=unpk(acc[i][0]), p1=unpk(acc[i][1]), p2=unpk(acc[i][2]), p3=unpk(acc[i][3]);
        float4 o0 = make_float4(p0.x+bsv[0], p0.y+bsv[1], p1.x+bsv[2], p1.y+bsv[3]);
        float4 o1 = make_float4(p2.x+bsv[4], p2.y+bsv[5], p3.x+bsv[6], p3.y+bsv[7]);
        if (relu){
            o0.x=fmaxf(o0.x,0.f); o0.y=fmaxf(o0.y,0.f); o0.z=fmaxf(o0.z,0.f); o0.w=fmaxf(o0.w,0.f);
            o1.x=fmaxf(o1.x,0.f); o1.y=fmaxf(o1.y,0.f); o1.z=fmaxf(o1.z,0.f); o1.w=fmaxf(o1.w,0.f);
        }
        *(float4*)&C[(size_t)m*N + n0    ] = o0;
        *(float4*)&C[(size_t)m*N + n0 + 4] = o1;
    }
}

// =====================================================================
// NHWC conv as tap-looped implicit GEMM, same engine. KS compile-time.
// in:[40000][IC]  wt:[KS*KS][IC][OC]  out:[40000][OC], H=W=200
// =====================================================================
template<int BN, int NT, int KS>
__global__ void __launch_bounds__(NT) conv2_k(
    const float* __restrict__ in, const float* __restrict__ wt,
    float* __restrict__ out, int IC, int OC, int pad)
{
    constexpr int TX  = BN/8;
    constexpr int AF4 = 512/NT;
    constexpr int BF4 = (16*BN/4)/NT;
    __shared__ float As[2][16][132];
    __shared__ float Bs[2][16][BN+4];
    __shared__ short spy[128], spx[128];

    int tid = threadIdx.x;
    int bm = blockIdx.y*128, bn = blockIdx.x*BN;
    int tx = tid % TX, ty = tid / TX;

    if (tid < 128){
        int p = bm + tid;
        if (p < 40000){ int py = p/200; spy[tid]=(short)py; spx[tid]=(short)(p-py*200); }
        else { spy[tid]=(short)10000; spx[tid]=0; }
    }
    __syncthreads();

    u64 acc[8][4];
    #pragma unroll
    for (int i=0;i<8;i++)
        #pragma unroll
        for (int j=0;j<4;j++) acc[i][j]=0ull;

    int kpt = IC >> 4;            // k-slabs per tap
    int S = KS*KS*kpt;
    float4 ar[AF4], br[BF4];

    // prologue: tap 0, k0 0
    {
        int dy = -pad, dx = -pad;
        #pragma unroll
        for (int j=0;j<AF4;j++){
            int idx = j*NT + tid; int row = idx>>2, kc = idx&3;
            int sy = spy[row]+dy, sx = spx[row]+dx;
            bool v = ((unsigned)sy < 200u) && ((unsigned)sx < 200u);
            ar[j] = v ? *(const float4*)&in[(size_t)(sy*200+sx)*IC + kc*4]
                      : make_float4(0.f,0.f,0.f,0.f);
        }
        #pragma unroll
        for (int j=0;j<BF4;j++){
            int idx = j*NT + tid; int kr = idx/(BN/4), cc = idx%(BN/4);
            int col = bn + cc*4;
            br[j] = (col < OC) ? *(const float4*)&wt[(size_t)kr*OC + col]
                               : make_float4(0.f,0.f,0.f,0.f);
        }
        #pragma unroll
        for (int j=0;j<AF4;j++){
            int idx = j*NT + tid; int row = idx>>2, kc = idx&3;
            As[0][kc*4+0][row]=ar[j].x; As[0][kc*4+1][row]=ar[j].y;
            As[0][kc*4+2][row]=ar[j].z; As[0][kc*4+3][row]=ar[j].w;
        }
        #pragma unroll
        for (int j=0;j<BF4;j++){
            int idx = j*NT + tid; int kr = idx/(BN/4), cc = idx%(BN/4);
            *(float4*)&Bs[0][kr][cc*4] = br[j];
        }
    }
    __syncthreads();

    int ltap = 0, lkq = 0;  // counters for NEXT slab
    for (int s=0; s<S; s++){
        int buf = s&1;
        if (s+1 < S){
            lkq++; if (lkq==kpt){ lkq=0; ltap++; }
            int k0 = lkq*16;
            int dy = ltap/KS - pad, dx = ltap%KS - pad;
            #pragma unroll
            for (int j=0;j<AF4;j++){
                int idx = j*NT + tid; int row = idx>>2, kc = idx&3;
                int sy = spy[row]+dy, sx = spx[row]+dx;
                bool v = ((unsigned)sy < 200u) && ((unsigned)sx < 200u);
                ar[j] = v ? *(const float4*)&in[(size_t)(sy*200+sx)*IC + k0 + kc*4]
                          : make_float4(0.f,0.f,0.f,0.f);
            }
            const float* wtap = wt + (size_t)ltap*IC*OC;
            #pragma unroll
            for (int j=0;j<BF4;j++){
                int idx = j*NT + tid; int kr = idx/(BN/4), cc = idx%(BN/4);
                int col = bn + cc*4;
                br[j] = (col < OC) ? *(const float4*)&wtap[(size_t)(k0+kr)*OC + col]
                                   : make_float4(0.f,0.f,0.f,0.f);
            }
        }
        #pragma unroll
        for (int kk=0;kk<16;kk++){
            float4 a0 = *(const float4*)&As[buf][kk][ty*8];
            float4 a1 = *(const float4*)&As[buf][kk][ty*8+4];
            ulonglong2 b01 = *(const ulonglong2*)&Bs[buf][kk][tx*8];
            ulonglong2 b23 = *(const ulonglong2*)&Bs[buf][kk][tx*8+4];
            u64 d;
            d=dup2(a0.x); acc[0][0]=ffma2(d,b01.x,acc[0][0]); acc[0][1]=ffma2(d,b01.y,acc[0][1]); acc[0][2]=ffma2(d,b23.x,acc[0][2]); acc[0][3]=ffma2(d,b23.y,acc[0][3]);
            d=dup2(a0.y); acc[1][0]=ffma2(d,b01.x,acc[1][0]); acc[1][1]=ffma2(d,b01.y,acc[1][1]); acc[1][2]=ffma2(d,b23.x,acc[1][2]); acc[1][3]=ffma2(d,b23.y,acc[1][3]);
            d=dup2(a0.z); acc[2][0]=ffma2(d,b01.x,acc[2][0]); acc[2][1]=ffma2(d,b01.y,acc[2][1]); acc[2][2]=ffma2(d,b23.x,acc[2][2]); acc[2][3]=ffma2(d,b23.y,acc[2][3]);
            d=dup2(a0.w); acc[3][0]=ffma2(d,b01.x,acc[3][0]); acc[3][1]=ffma2(d,b01.y,acc[3][1]); acc[3][2]=ffma2(d,b23.x,acc[3][2]); acc[3][3]=ffma2(d,b23.y,acc[3][3]);
            d=dup2(a1.x); acc[4][0]=ffma2(d,b01.x,acc[4][0]); acc[4][1]=ffma2(d,b01.y,acc[4][1]); acc[4][2]=ffma2(d,b23.x,acc[4][2]); acc[4][3]=ffma2(d,b23.y,acc[4][3]);
            d=dup2(a1.y); acc[5][0]=ffma2(d,b01.x,acc[5][0]); acc[5][1]=ffma2(d,b01.y,acc[5][1]); acc[5][2]=ffma2(d,b23.x,acc[5][2]); acc[5][3]=ffma2(d,b23.y,acc[5][3]);
            d=dup2(a1.z); acc[6][0]=ffma2(d,b01.x,acc[6][0]); acc[6][1]=ffma2(d,b01.y,acc[6][1]); acc[6][2]=ffma2(d,b23.x,acc[6][2]); acc[6][3]=ffma2(d,b23.y,acc[6][3]);
            d=dup2(a1.w); acc[7][0]=ffma2(d,b01.x,acc[7][0]); acc[7][1]=ffma2(d,b01.y,acc[7][1]); acc[7][2]=ffma2(d,b23.x,acc[7][2]); acc[7][3]=ffma2(d,b23.y,acc[7][3]);
        }
        if (s+1 < S){
            int nb = buf^1;
            #pragma unroll
            for (int j=0;j<AF4;j++){
                int idx = j*NT + tid; int row = idx>>2, kc = idx&3;
                As[nb][kc*4+0][row]=ar[j].x; As[nb][kc*4+1][row]=ar[j].y;
                As[nb][kc*4+2][row]=ar[j].z; As[nb][kc*4+3][row]=ar[j].w;
            }
            #pragma unroll
            for (int j=0;j<BF4;j++){
                int idx = j*NT + tid; int kr = idx/(BN/4), cc = idx%(BN/4);
                *(float4*)&Bs[nb][kr][cc*4] = br[j];
            }
        }
        __syncthreads();
    }

    // epilogue (no bias, no relu; BN stats follow)
    int n0 = bn + tx*8;
    #pragma unroll
    for (int i=0;i<8;i++){
        int m = bm + ty*8 + i;
        if (m >= 40000) continue;
        float2 p0=unpk(acc[i][0]), p1=unpk(acc[i][1]), p2=unpk(acc[i][2]), p3=unpk(acc[i][3]);
        if (n0 < OC)
            *(float4*)&out[(size_t)m*OC + n0] = make_float4(p0.x,p0.y,p1.x,p1.y);
        if (n0+4 < OC)
            *(float4*)&out[(size_t)m*OC + n0 + 4] = make_float4(p2.x,p2.y,p3.x,p3.y);
    }
}

// ---------------- softmax over 32 (per query,head) ----------------
__global__ void softmax32_k(float* __restrict__ a){
    int warp = threadIdx.x>>5, lane = threadIdx.x&31;
    int row = blockIdx.x*8 + warp;
    float v = a[(size_t)row*32 + lane];
    float m = v;
    #pragma unroll
    for (int o=16;o>0;o>>=1) m = fmaxf(m, __shfl_xor_sync(0xffffffffu, m, o));
    float e = expf(v - m);
    float s = e;
    #pragma unroll
    for (int o=16;o>0;o>>=1) s += __shfl_xor_sync(0xffffffffu, s, o);
    a[(size_t)row*32 + lane] = e / s;
}

// ---------------- deformable bilinear sampling ----------------
__global__ void __launch_bounds__(256) sample_k(
    const float* __restrict__ v, const float* __restrict__ off,
    const float* __restrict__ aw, float* __restrict__ samp)
{
    int t = blockIdx.x*256 + threadIdx.x;
    if (t >= NQc*EDc) return;
    int q = t >> 7, r = t & 127, h = r >> 4, d = r & 15;
    float refx = ((float)(q % 200) + 0.5f) * (1.f/200.f);
    float refy = ((float)(q / 200) + 0.5f) * (1.f/200.f);
    const float* op = off + (size_t)(q*8 + h)*64;
    const float* ap = aw  + (size_t)(q*8 + h)*32;
    const int ch = h*16 + d;
    const int Ws_[4]={256,128,64,32};
    const int Hs_[4]={128,64,32,16};
    const int Bs_[4]={0,32768,40960,43008};
    float acc = 0.f;
    #pragma unroll
    for (int l=0;l<4;l++){
        int W=Ws_[l], Hh=Hs_[l], base=Bs_[l];
        float fW=(float)W, fH=(float)Hh;
        #pragma unroll
        for (int p=0;p<8;p++){
            float ox = op[l*16 + p*2];
            float oy = op[l*16 + p*2 + 1];
            float x = refx*fW + ox - 0.5f;
            float y = refy*fH + oy - 0.5f;
            float x0f = floorf(x), y0f = floorf(y);
            int x0 = (int)x0f, y0 = (int)y0f;
            float fx = x - x0f, fy = y - y0f;
            float a = ap[l*8 + p];
            float s = 0.f;
            if (y0 >= 0 && y0 < Hh){
                int rowb = base + y0*W;
                if (x0   >= 0 && x0   < W) s += (1.f-fx)*(1.f-fy) * v[(size_t)(rowb+x0  )*128 + ch];
                if (x0+1 >= 0 && x0+1 < W) s += fx*(1.f-fy)       * v[(size_t)(rowb+x0+1)*128 + ch];
            }
            int y1 = y0+1;
            if (y1 >= 0 && y1 < Hh){
                int rowb = base + y1*W;
                if (x0   >= 0 && x0   < W) s += (1.f-fx)*fy * v[(size_t)(rowb+x0  )*128 + ch];
                if (x0+1 >= 0 && x0+1 < W) s += fx*fy       * v[(size_t)(rowb+x0+1)*128 + ch];
            }
            acc += a * s;
        }
    }
    samp[(size_t)q*128 + h*16 + d] = acc;
}

// ---------------- residual + LayerNorm (in-place on q) ----------------
__global__ void ln_res_k(float* __restrict__ q, const float* __restrict__ r,
                         const float* __restrict__ g, const float* __restrict__ b)
{
    int row = blockIdx.x, c = threadIdx.x;
    size_t idx = (size_t)row*128 + c;
    float x = q[idx] + r[idx];
    __shared__ float sm[4];
    float s = x;
    #pragma unroll
    for (int o=16;o>0;o>>=1) s += __shfl_xor_sync(0xffffffffu, s, o);
    if ((c&31)==0) sm[c>>5]=s;
    __syncthreads();
    float mean = (sm[0]+sm[1]+sm[2]+sm[3]) * (1.f/128.f);
    __syncthreads();
    float dlt = x - mean;
    float s2 = dlt*dlt;
    #pragma unroll
    for (int o=16;o>0;o>>=1) s2 += __shfl_xor_sync(0xffffffffu, s2, o);
    if ((c&31)==0) sm[c>>5]=s2;
    __syncthreads();
    float var = (sm[0]+sm[1]+sm[2]+sm[3]) * (1.f/128.f);
    q[idx] = dlt * rsqrtf(var + 1e-5f) * g[c] + b[c];
}

// ---------------- weight transpose: OIHW -> [tap][IC][OC] ----------------
__global__ void transpose_w_k(const float* __restrict__ w, float* __restrict__ wt,
                              int OC, int IC, int KS, int total)
{
    int i = blockIdx.x*256 + threadIdx.x;
    if (i >= total) return;
    int ksks = KS*KS;
    int oc = i / (IC*ksks);
    int rem = i - oc*IC*ksks;
    int ic = rem / ksks;
    int tap = rem - ic*ksks;
    wt[(size_t)tap*IC*OC + (size_t)ic*OC + oc] = w[i];
}

// ---------------- BN stats (deterministic 2-stage) + apply ----------------
__global__ void bn_partial_k(const float* __restrict__ x, int C, float* __restrict__ part){
    int c = threadIdx.x, b = blockIdx.x;
    int p0 = b*250;
    float s=0.f, q=0.f;
    for (int p=0;p<250;p++){
        float v = x[(size_t)(p0+p)*C + c];
        s += v; q += v*v;
    }
    part[(size_t)b*C + c] = s;
    part[(size_t)(160+b)*C + c] = q;
}
__global__ void bn_finish_k(const float* __restrict__ part, const float* __restrict__ g,
                            const float* __restrict__ bb, float* __restrict__ scale,
                            float* __restrict__ shift, int C)
{
    int c = threadIdx.x;
    float s=0.f, q=0.f;
    for (int b=0;b<160;b++){ s += part[(size_t)b*C + c]; q += part[(size_t)(160+b)*C + c]; }
    float m = s * (1.f/40000.f);
    float v = q * (1.f/40000.f) - m*m;
    float sc = g[c] * rsqrtf(v + 1e-5f);
    scale[c] = sc;
    shift[c] = bb[c] - m*sc;
}
__global__ void bn_apply_k(float* __restrict__ x, const float* __restrict__ scale,
                           const float* __restrict__ shift, int C, int total)
{
    int i = blockIdx.x*256 + threadIdx.x;
    if (i >= total) return;
    int c = i % C;
    x[i] = fmaxf(x[i]*scale[c] + shift[c], 0.f);
}

// ---------------- final 1x1 conv (48 -> 21), NCHW output ----------------
__global__ void conv5_k(const float* __restrict__ h4, const float* __restrict__ w,
                        const float* __restrict__ b, float* __restrict__ out)
{
    int t = blockIdx.x*256 + threadIdx.x;
    int p = t >> 5, cls = t & 31;
    if (p >= 40000 || cls >= 21) return;
    const float* hr = h4 + (size_t)p*48;
    const float* wr = w + cls*48;
    float s = b[cls];
    #pragma unroll
    for (int c=0;c<48;c++) s += hr[c]*wr[c];
    out[(size_t)cls*40000 + p] = s;
}

// ==================================================================
extern "C" void kernel_launch(void* const* d_in, const int* in_sizes, int n_in,
                              void* d_out, int out_size)
{
    const float* value = (const float*)d_in[0];
    const float* bq    = (const float*)d_in[1];
    const float* bpos  = (const float*)d_in[2];
    const int*   proj  = (const int*)  d_in[3];
    const float* Wv    = (const float*)d_in[4];
    const float* bv    = (const float*)d_in[5];
    const float* Woff  = (const float*)d_in[6];
    const float* boff  = (const float*)d_in[7];
    const float* Wattn = (const float*)d_in[8];
    const float* battn = (const float*)d_in[9];
    const float* Wout  = (const float*)d_in[10];
    const float* bout  = (const float*)d_in[11];
    const float* Wf1   = (const float*)d_in[12];
    const float* bf1   = (const float*)d_in[13];
    const float* Wf2   = (const float*)d_in[14];
    const float* bf2   = (const float*)d_in[15];
    const float* lng   = (const float*)d_in[16];
    const float* lnb   = (const float*)d_in[17];
    const float* cw1   = (const float*)d_in[18];
    const float* g1    = (const float*)d_in[19];
    const float* b1    = (const float*)d_in[20];
    const float* cw2   = (const float*)d_in[21];
    const float* g2    = (const float*)d_in[22];
    const float* b2    = (const float*)d_in[23];
    const float* cw3   = (const float*)d_in[24];
    const float* g3    = (const float*)d_in[25];
    const float* b3    = (const float*)d_in[26];
    const float* cw4   = (const float*)d_in[27];
    const float* g4    = (const float*)d_in[28];
    const float* b4    = (const float*)d_in[29];
    const float* objw  = (const float*)d_in[30];
    const float* objb  = (const float*)d_in[31];
    float* out = (float*)d_out;

    float *p_q,*p_qin,*p_v,*p_off,*p_aw,*p_samp,*p_t1,*p_t2;
    float *p_c1,*p_c2,*p_c3,*p_c4,*p_wt,*p_part,*p_scale,*p_shift;
    cudaGetSymbolAddress((void**)&p_q,    g_q);
    cudaGetSymbolAddress((void**)&p_qin,  g_qin);
    cudaGetSymbolAddress((void**)&p_v,    g_v);
    cudaGetSymbolAddress((void**)&p_off,  g_off);
    cudaGetSymbolAddress((void**)&p_aw,   g_aw);
    cudaGetSymbolAddress((void**)&p_samp, g_samp);
    cudaGetSymbolAddress((void**)&p_t1,   g_t1);
    cudaGetSymbolAddress((void**)&p_t2,   g_t2);
    cudaGetSymbolAddress((void**)&p_c1,   g_c1);
    cudaGetSymbolAddress((void**)&p_c2,   g_c2);
    cudaGetSymbolAddress((void**)&p_c3,   g_c3);
    cudaGetSymbolAddress((void**)&p_c4,   g_c4);
    cudaGetSymbolAddress((void**)&p_wt,   g_wt);
    cudaGetSymbolAddress((void**)&p_part, g_part);
    cudaGetSymbolAddress((void**)&p_scale,g_scale);
    cudaGetSymbolAddress((void**)&p_shift,g_shift);

    const int NE = NQc*EDc;            // 5,120,000
    const int EB = (NE+255)/256;       // 20000
    const int GM = 313;                // ceil(40000/128)

    // ---- observed_masks ----
    set_min_k<<<1,1>>>();
    rmax_k<<<(40000+255)/256,256>>>(proj, 40000);
    if (out_size >= 880000)
        wmask_k<<<(40000+255)/256,256>>>(proj, out + 840000, 40000);

    // ---- encoder ----
    copy_k<<<EB,256>>>(p_q, bq, NE);
    for (int i=0;i<2;i++){
        add_k<<<EB,256>>>(p_qin, p_q, bpos, NE);
        gemm2_k<128,256><<<dim3(1,340),256>>>(value, Wv + (size_t)i*EDc*EDc, bv + i*EDc, p_v, NVc, EDc, EDc, 0);
        gemm2_k<128,256><<<dim3(4,GM),256>>>(p_qin, Woff + (size_t)i*EDc*512, boff + i*512, p_off, NQc, 512, EDc, 0);
        gemm2_k<128,256><<<dim3(2,GM),256>>>(p_qin, Wattn + (size_t)i*EDc*256, battn + i*256, p_aw, NQc, 256, EDc, 0);
        softmax32_k<<<40000,256>>>(p_aw);
        sample_k<<<EB,256>>>(p_v, p_off, p_aw, p_samp);
        gemm2_k<128,256><<<dim3(1,GM),256>>>(p_samp, Wout + (size_t)i*EDc*EDc, bout + i*EDc, p_t1, NQc, EDc, EDc, 0);
        ln_res_k<<<40000,128>>>(p_q, p_t1, lng + (i*2+0)*EDc, lnb + (i*2+0)*EDc);
        gemm2_k<128,256><<<dim3(1,GM),256>>>(p_q, Wf1 + (size_t)i*EDc*EDc, bf1 + i*EDc, p_t1, NQc, EDc, EDc, 1);
        gemm2_k<128,256><<<dim3(1,GM),256>>>(p_t1, Wf2 + (size_t)i*EDc*EDc, bf2 + i*EDc, p_t2, NQc, EDc, EDc, 0);
        ln_res_k<<<40000,128>>>(p_q, p_t2, lng + (i*2+1)*EDc, lnb + (i*2+1)*EDc);
    }

    // ---- conv head (NHWC) ----
    // conv1: 128->128, 7x7, pad 3
    transpose_w_k<<<(49*128*128+255)/256,256>>>(cw1, p_wt, 128, 128, 7, 49*128*128);
    conv2_k<128,256,7><<<dim3(1,GM),256>>>(p_q, p_wt, p_c1, 128, 128, 3);
    bn_partial_k<<<160,128>>>(p_c1, 128, p_part);
    bn_finish_k<<<1,128>>>(p_part, g1, b1, p_scale, p_shift, 128);
    bn_apply_k<<<(40000*128)/256,256>>>(p_c1, p_scale, p_shift, 128, 40000*128);

    // conv2: 128->64, 3x3, pad 1
    transpose_w_k<<<(9*128*64+255)/256,256>>>(cw2, p_wt, 64, 128, 3, 9*128*64);
    conv2_k<64,128,3><<<dim3(1,GM),128>>>(p_c1, p_wt, p_c2, 128, 64, 1);
    bn_partial_k<<<160,64>>>(p_c2, 64, p_part);
    bn_finish_k<<<1,64>>>(p_part, g2, b2, p_scale, p_shift, 64);
    bn_apply_k<<<(40000*64)/256,256>>>(p_c2, p_scale, p_shift, 64, 40000*64);

    // conv3: 64->48, 3x3, pad 1
    transpose_w_k<<<(9*64*48+255)/256,256>>>(cw3, p_wt, 48, 64, 3, 9*64*48);
    conv2_k<64,128,3><<<dim3(1,GM),128>>>(p_c2, p_wt, p_c3, 64, 48, 1);
    bn_partial_k<<<160,48>>>(p_c3, 48, p_part);
    bn_finish_k<<<1,48>>>(p_part, g3, b3, p_scale, p_shift, 48);
    bn_apply_k<<<(40000*48)/256,256>>>(p_c3, p_scale, p_shift, 48, 40000*48);

    // conv4: 48->48, 3x3, pad 1
    transpose_w_k<<<(9*48*48+255)/256,256>>>(cw4, p_wt, 48, 48, 3, 9*48*48);
    conv2_k<64,128,3><<<dim3(1,GM),128>>>(p_c3, p_wt, p_c4, 48, 48, 1);
    bn_partial_k<<<160,48>>>(p_c4, 48, p_part);
    bn_finish_k<<<1,48>>>(p_part, g4, b4, p_scale, p_shift, 48);
    bn_apply_k<<<(40000*48)/256,256>>>(p_c4, p_scale, p_shift, 48, 40000*48);

    // final 1x1 conv -> semmap
    conv5_k<<<(40000*32)/256,256>>>(p_c4, objw, objb, out);
}